// round 4
// baseline (speedup 1.0000x reference)
#include <cuda_runtime.h>
#include <stdint.h>

// ---------------- problem constants ----------------
#define NKEY 220000          // 4 * 220 * 250 dense merge-key space
#define MAXN 1048576         // >= 1e6 points
#define SCAN_BLK 215         // ceil(220000 / 1024)

// ---------------- persistent device scratch ----------------
__device__ int   g_cnt[NKEY];
__device__ float g_sumx[NKEY], g_sumy[NKEY], g_sumz[NKEY];
__device__ int   g_cursor[NKEY];
__device__ int   g_start[NKEY];
__device__ int   g_rank[NKEY];
__device__ int   g_voxstart[NKEY + 1];
__device__ unsigned long long g_bsum[SCAN_BLK];
__device__ unsigned long long g_boff[SCAN_BLK];
__device__ int   g_keys[MAXN];
__device__ int   g_posvox[MAXN];
__device__ float g_ybuf[(size_t)MAXN * 32];    // stage-1 pre-BN activations, voxel-sorted (later overwritten with h)
__device__ float g_zbuf[(size_t)MAXN * 128];   // stage-2 pre-BN activations, voxel-sorted
__device__ float g_xmax[(size_t)NKEY * 32];
__device__ double g_s1[32], g_q1[32];
__device__ double g_s2[128], g_q2[128];
__device__ float g_a1[32], g_b1v[32];
__device__ float g_a2[128], g_b2v[128];
__device__ int   g_Nm;

// ---------------- K0: reset ----------------
__global__ void kzero() {
    int i = blockIdx.x * blockDim.x + threadIdx.x;
    if (i < NKEY) {
        g_cnt[i] = 0; g_cursor[i] = 0;
        g_sumx[i] = 0.f; g_sumy[i] = 0.f; g_sumz[i] = 0.f;
    }
    if (i < 32)  { g_s1[i] = 0.0; g_q1[i] = 0.0; }
    if (i < 128) { g_s2[i] = 0.0; g_q2[i] = 0.0; }
    if (i == 0)  g_Nm = 0;
}

// ---------------- K1: voxelize points, per-key count + xyz sums ----------------
__global__ void k1(const float* __restrict__ pts, int n) {
    int i = blockIdx.x * blockDim.x + threadIdx.x;
    int valid = 0;
    if (i < n) {
        float bf = pts[i * 5 + 0];
        float x  = pts[i * 5 + 1];
        float y  = pts[i * 5 + 2];
        float z  = pts[i * 5 + 3];
        int cx = (int)floorf(__fdiv_rn(x - 0.0f, 0.32f));
        int cy = (int)floorf(__fdiv_rn(y + 40.0f, 0.32f));
        int cz = (int)floorf(__fdiv_rn(z + 3.0f, 4.0f));
        int key = -1;
        if (cx >= 0 && cx < 220 && cy >= 0 && cy < 250 && cz >= 0 && cz < 1) {
            key = (int)bf * 55000 + cx * 250 + cy + cz;
            atomicAdd(&g_cnt[key], 1);
            atomicAdd(&g_sumx[key], x);
            atomicAdd(&g_sumy[key], y);
            atomicAdd(&g_sumz[key], z);
            valid = 1;
        }
        g_keys[i] = key;
    }
    int c = __syncthreads_count(valid);
    if (threadIdx.x == 0) atomicAdd(&g_Nm, c);
}

// ---------------- K2: dual exclusive scan over dense key space ----------------
// packed u64: high 32 = occupancy flag, low 32 = point count.
__global__ void k2a() {
    __shared__ unsigned long long sh[256];
    int base = blockIdx.x * 1024;
    int t = threadIdx.x;
    unsigned long long s = 0;
    #pragma unroll
    for (int j = 0; j < 4; j++) {
        int k = base + t * 4 + j;
        if (k < NKEY) {
            unsigned c = (unsigned)g_cnt[k];
            s += (((unsigned long long)(c > 0)) << 32) | (unsigned long long)c;
        }
    }
    sh[t] = s; __syncthreads();
    for (int off = 128; off > 0; off >>= 1) {
        if (t < off) sh[t] += sh[t + off];
        __syncthreads();
    }
    if (t == 0) g_bsum[blockIdx.x] = sh[0];
}

__global__ void k2b() {
    __shared__ unsigned long long sh[256];
    int t = threadIdx.x;
    unsigned long long v = (t < SCAN_BLK) ? g_bsum[t] : 0ull;
    sh[t] = v; __syncthreads();
    for (int off = 1; off < 256; off <<= 1) {
        unsigned long long a = (t >= off) ? sh[t - off] : 0ull;
        __syncthreads();
        sh[t] += a;
        __syncthreads();
    }
    if (t < SCAN_BLK) g_boff[t] = sh[t] - v;   // exclusive
}

__global__ void k2c(float* __restrict__ coords_out, int V) {
    __shared__ unsigned long long sh[256];
    int base = blockIdx.x * 1024;
    int t = threadIdx.x;
    int k0 = base + t * 4;
    unsigned long long loc[4];
    unsigned long long s = 0;
    #pragma unroll
    for (int j = 0; j < 4; j++) {
        int k = k0 + j;
        unsigned long long v = 0;
        if (k < NKEY) {
            unsigned c = (unsigned)g_cnt[k];
            v = (((unsigned long long)(c > 0)) << 32) | (unsigned long long)c;
        }
        loc[j] = s; s += v;
    }
    sh[t] = s; __syncthreads();
    for (int off = 1; off < 256; off <<= 1) {
        unsigned long long a = (t >= off) ? sh[t - off] : 0ull;
        __syncthreads();
        sh[t] += a;
        __syncthreads();
    }
    unsigned long long texcl = sh[t] - s + g_boff[blockIdx.x];
    #pragma unroll
    for (int j = 0; j < 4; j++) {
        int k = k0 + j;
        if (k >= NKEY) break;
        unsigned long long e = texcl + loc[j];
        int start = (int)(e & 0xffffffffull);
        int rank  = (int)(e >> 32);
        g_start[k] = start;
        if (g_cnt[k] > 0) {
            g_rank[k] = rank;
            g_voxstart[rank] = start;
            int b = k / 55000, rem = k % 55000;
            int cx = rem / 250, cy = rem % 250;
            if (rank < V) {
                float4 co = make_float4((float)b, 0.f, (float)cy, (float)cx);
                *(float4*)(coords_out + (size_t)rank * 4) = co;
            }
        }
    }
}

// ---------------- K3: feats -> y = feats@w0, BN1 stats, scatter into voxel order ----------------
__global__ void __launch_bounds__(256) k3(const float* __restrict__ pts,
                                          const float* __restrict__ w0, int n) {
    __shared__ float ws[10][32];
    __shared__ float sy[8][32][33];
    __shared__ int   spos[8][32];
    __shared__ int   svox[8][32];
    __shared__ float ssum[32], ssq[32];
    int t = threadIdx.x;
    for (int idx = t; idx < 320; idx += 256)      // FIX: full 10x32 weight load
        ws[idx / 32][idx % 32] = w0[idx];
    if (t < 32) { ssum[t] = 0.f; ssq[t] = 0.f; }
    __syncthreads();

    int i = blockIdx.x * blockDim.x + t;
    int warp = t >> 5, lane = t & 31;
    int key = (i < n) ? g_keys[i] : -1;
    float y[32];
    int pos = -1, r = 0;
    if (key >= 0) {
        float x  = pts[i * 5 + 1];
        float yy = pts[i * 5 + 2];
        float z  = pts[i * 5 + 3];
        float it = pts[i * 5 + 4];
        float c  = (float)g_cnt[key];
        float mx = g_sumx[key] / c, my = g_sumy[key] / c, mz = g_sumz[key] / c;
        int rem = key % 55000;
        int cx = rem / 250, cy = rem % 250;
        float ff[10];
        ff[0] = x; ff[1] = yy; ff[2] = z; ff[3] = it;
        ff[4] = x - mx; ff[5] = yy - my; ff[6] = z - mz;
        ff[7] = x - ((float)cx * 0.32f + 0.16f);
        ff[8] = yy - ((float)cy * 0.32f - 39.84f);
        ff[9] = z + 1.0f;
        #pragma unroll
        for (int c2 = 0; c2 < 32; c2++) {
            float a = 0.f;
            #pragma unroll
            for (int j = 0; j < 10; j++) a = fmaf(ff[j], ws[j][c2], a);
            y[c2] = a;
        }
        r = g_rank[key];
        pos = g_start[key] + atomicAdd(&g_cursor[key], 1);
    } else {
        #pragma unroll
        for (int c2 = 0; c2 < 32; c2++) y[c2] = 0.f;   // contributes 0 to stats: harmless
    }

    // BN1 stats: warp butterfly reduce per channel, one lane commits to shared
    #pragma unroll
    for (int c2 = 0; c2 < 32; c2++) {
        float v = y[c2], q = v * v;
        #pragma unroll
        for (int o = 16; o > 0; o >>= 1) {
            v += __shfl_xor_sync(0xffffffffu, v, o);
            q += __shfl_xor_sync(0xffffffffu, q, o);
        }
        if (lane == c2) { atomicAdd(&ssum[c2], v); atomicAdd(&ssq[c2], q); }
    }

    // scatter y into voxel-sorted order via padded smem transpose (coalesced 128B stores)
    #pragma unroll
    for (int c2 = 0; c2 < 32; c2++) sy[warp][lane][c2] = y[c2];
    spos[warp][lane] = pos;
    svox[warp][lane] = r;
    __syncwarp();
    for (int p = 0; p < 32; p++) {
        int dp = spos[warp][p];
        if (dp >= 0) {
            g_ybuf[(size_t)dp * 32 + lane] = sy[warp][p][lane];
            if (lane == 0) g_posvox[dp] = svox[warp][p];
        }
    }
    __syncthreads();
    if (t < 32) {
        atomicAdd(&g_s1[t], (double)ssum[t]);
        atomicAdd(&g_q1[t], (double)ssq[t]);
    }
}

// ---------------- K4: finalize BN1 params ----------------
__global__ void k4(const float* __restrict__ g0, const float* __restrict__ b0, int V) {
    int t = threadIdx.x;
    if (t == 0) g_voxstart[V] = g_Nm;   // CSR sentinel
    if (t < 32) {
        double nn = (double)g_Nm;
        double m = g_s1[t] / nn;
        double var = g_q1[t] / nn - m * m;
        float s = (float)((double)g0[t] / sqrt(var + 0.001));
        g_a1[t] = s;
        g_b1v[t] = b0[t] - (float)m * s;
    }
}

// ---------------- K5: BN1+ReLU in place, per-voxel xmax (warp per voxel, lane=channel) ----------------
__global__ void k5(int V) {
    int w = (blockIdx.x * blockDim.x + threadIdx.x) >> 5;
    int lane = threadIdx.x & 31;
    if (w >= V) return;
    int s0 = g_voxstart[w], s1 = g_voxstart[w + 1];
    float a = g_a1[lane], b = g_b1v[lane];
    float m = 0.f;
    for (int p = s0; p < s1; p++) {
        float yv = g_ybuf[(size_t)p * 32 + lane];
        float h = fmaxf(fmaf(a, yv, b), 0.f);
        g_ybuf[(size_t)p * 32 + lane] = h;
        m = fmaxf(m, h);
    }
    g_xmax[(size_t)w * 32 + lane] = m;
}

// ---------------- K6: z = [h | xmax] @ w1  (tiled 128pts x 128ch, 8x8 per thread) ----------------
__global__ void __launch_bounds__(256) k6(const float* __restrict__ w1) {
    extern __shared__ float sm[];
    float* xs  = sm;             // [64][128] k-major, point contiguous
    float* wsh = sm + 64 * 128;  // [64][128]
    int t = threadIdx.x;
    int Nm = g_Nm;
    int P0 = blockIdx.x * 128;
    if (P0 >= Nm) return;

    for (int idx = t * 4; idx < 64 * 128; idx += 256 * 4)
        *(float4*)&wsh[idx] = *(const float4*)&w1[idx];

    {
        int p = t & 127, half = t >> 7;
        int gp = P0 + p;
        if (half == 0) {
            if (gp < Nm) {
                const float4* src = (const float4*)&g_ybuf[(size_t)gp * 32];
                #pragma unroll
                for (int q = 0; q < 8; q++) {
                    float4 v = src[q];
                    xs[(q * 4 + 0) * 128 + p] = v.x;
                    xs[(q * 4 + 1) * 128 + p] = v.y;
                    xs[(q * 4 + 2) * 128 + p] = v.z;
                    xs[(q * 4 + 3) * 128 + p] = v.w;
                }
            } else {
                #pragma unroll
                for (int k = 0; k < 32; k++) xs[k * 128 + p] = 0.f;
            }
        } else {
            if (gp < Nm) {
                int vx = g_posvox[gp];
                const float4* src = (const float4*)&g_xmax[(size_t)vx * 32];
                #pragma unroll
                for (int q = 0; q < 8; q++) {
                    float4 v = src[q];
                    xs[(32 + q * 4 + 0) * 128 + p] = v.x;
                    xs[(32 + q * 4 + 1) * 128 + p] = v.y;
                    xs[(32 + q * 4 + 2) * 128 + p] = v.z;
                    xs[(32 + q * 4 + 3) * 128 + p] = v.w;
                }
            } else {
                #pragma unroll
                for (int k = 32; k < 64; k++) xs[k * 128 + p] = 0.f;
            }
        }
    }
    __syncthreads();

    int ty = t >> 4, tx = t & 15;
    float acc[8][8];
    #pragma unroll
    for (int i2 = 0; i2 < 8; i2++)
        #pragma unroll
        for (int j2 = 0; j2 < 8; j2++) acc[i2][j2] = 0.f;

    #pragma unroll 4
    for (int k = 0; k < 64; k++) {
        float4 xa = *(float4*)&xs[k * 128 + ty * 8];
        float4 xb = *(float4*)&xs[k * 128 + ty * 8 + 4];
        float4 wa = *(float4*)&wsh[k * 128 + tx * 8];
        float4 wb = *(float4*)&wsh[k * 128 + tx * 8 + 4];
        float xr[8] = {xa.x, xa.y, xa.z, xa.w, xb.x, xb.y, xb.z, xb.w};
        float wr[8] = {wa.x, wa.y, wa.z, wa.w, wb.x, wb.y, wb.z, wb.w};
        #pragma unroll
        for (int i2 = 0; i2 < 8; i2++)
            #pragma unroll
            for (int j2 = 0; j2 < 8; j2++)
                acc[i2][j2] = fmaf(xr[i2], wr[j2], acc[i2][j2]);
    }

    int nv = Nm - P0;
    #pragma unroll
    for (int i2 = 0; i2 < 8; i2++) {
        int p = ty * 8 + i2;
        if (p < nv) {
            float* dst = &g_zbuf[((size_t)(P0 + p)) * 128 + tx * 8];
            *(float4*)dst       = make_float4(acc[i2][0], acc[i2][1], acc[i2][2], acc[i2][3]);
            *(float4*)(dst + 4) = make_float4(acc[i2][4], acc[i2][5], acc[i2][6], acc[i2][7]);
        }
    }
}

// ---------------- K6b: BN2 stats over z ----------------
__global__ void k6b() {
    int Nm = g_Nm;
    int tid = blockIdx.x * blockDim.x + threadIdx.x;
    int c = tid & 127;
    int row = tid >> 7;
    int stride = (gridDim.x * blockDim.x) >> 7;
    float s = 0.f, q = 0.f;
    for (int r = row; r < Nm; r += stride) {
        float z = g_zbuf[(size_t)r * 128 + c];
        s += z; q += z * z;
    }
    atomicAdd(&g_s2[c], (double)s);
    atomicAdd(&g_q2[c], (double)q);
}

// ---------------- K7: finalize BN2 params ----------------
__global__ void k7(const float* __restrict__ g1, const float* __restrict__ b1) {
    int t = threadIdx.x;
    double nn = (double)g_Nm;
    double m = g_s2[t] / nn;
    double var = g_q2[t] / nn - m * m;
    float s = (float)((double)g1[t] / sqrt(var + 0.001));
    g_a2[t] = s;
    g_b2v[t] = b1[t] - (float)m * s;
}

// ---------------- K8: BN2+ReLU + per-voxel max -> pillar_feat ----------------
__global__ void k8(float* __restrict__ out, int V) {
    int w = (blockIdx.x * blockDim.x + threadIdx.x) >> 5;
    int lane = threadIdx.x & 31;
    if (w >= V) return;
    int s0 = g_voxstart[w], s1 = g_voxstart[w + 1];
    float4 a = *(float4*)&g_a2[lane * 4];
    float4 b = *(float4*)&g_b2v[lane * 4];
    float4 m = make_float4(0.f, 0.f, 0.f, 0.f);
    for (int p = s0; p < s1; p++) {
        float4 z = *(float4*)&g_zbuf[(size_t)p * 128 + lane * 4];
        m.x = fmaxf(m.x, fmaxf(fmaf(a.x, z.x, b.x), 0.f));
        m.y = fmaxf(m.y, fmaxf(fmaf(a.y, z.y, b.y), 0.f));
        m.z = fmaxf(m.z, fmaxf(fmaf(a.z, z.z, b.z), 0.f));
        m.w = fmaxf(m.w, fmaxf(fmaf(a.w, z.w, b.w), 0.f));
    }
    *(float4*)&out[(size_t)w * 128 + lane * 4] = m;
}

// ---------------- host entry ----------------
extern "C" void kernel_launch(void* const* d_in, const int* in_sizes, int n_in,
                              void* d_out, int out_size) {
    const float* pts = (const float*)d_in[0];
    const float* w0  = (const float*)d_in[1];
    const float* g0  = (const float*)d_in[2];
    const float* b0  = (const float*)d_in[3];
    const float* w1  = (const float*)d_in[4];
    const float* g1  = (const float*)d_in[5];
    const float* b1  = (const float*)d_in[6];
    float* out = (float*)d_out;

    int n = in_sizes[0] / 5;
    if (n > MAXN) n = MAXN;
    int V = out_size / 132;   // output = [pillar_feat V*128 | pillar_coords V*4]

    cudaFuncSetAttribute(k6, cudaFuncAttributeMaxDynamicSharedMemorySize, 65536);

    kzero<<<(NKEY + 255) / 256, 256>>>();
    k1<<<(n + 255) / 256, 256>>>(pts, n);
    k2a<<<SCAN_BLK, 256>>>();
    k2b<<<1, 256>>>();
    k2c<<<SCAN_BLK, 256>>>(out + (size_t)V * 128, V);
    k3<<<(n + 255) / 256, 256>>>(pts, w0, n);
    k4<<<1, 32>>>(g0, b0, V);
    k5<<<(V + 7) / 8, 256>>>(V);
    k6<<<(n + 127) / 128, 256, 65536>>>(w1);
    k6b<<<512, 256>>>();
    k7<<<1, 128>>>(g1, b1);
    k8<<<(V + 7) / 8, 256>>>(out, V);
}

// round 6
// speedup vs baseline: 1.3061x; 1.3061x over previous
#include <cuda_runtime.h>
#include <stdint.h>

// ---------------- problem constants ----------------
#define NKEY 220000          // 4 * 220 * 250 dense merge-key space
#define MAXN 1048576         // >= 1e6 points
#define SCAN_BLK 215         // ceil(220000 / 1024)
#define NBLK_MAX (MAXN / 128)

// ---------------- packed fp32x2 helpers (Blackwell 2xFP32 path) ----------------
#define FFMA2(d, a, b, c) \
    asm("fma.rn.f32x2 %0, %1, %2, %3;" : "=l"(d) : "l"(a), "l"(b), "l"(c))
#define PACKXX(d, x) \
    asm("mov.b64 %0, {%1, %1};" : "=l"(d) : "f"(x))

// ---------------- persistent device scratch ----------------
__device__ int   g_cnt[NKEY];
__device__ float g_sumx[NKEY], g_sumy[NKEY], g_sumz[NKEY];
__device__ int   g_cursor[NKEY];
__device__ int   g_start[NKEY];
__device__ int   g_rank[NKEY];
__device__ int   g_voxstart[NKEY + 1];
__device__ unsigned long long g_bsum[SCAN_BLK];
__device__ unsigned long long g_boff[SCAN_BLK];
__device__ int   g_keys[MAXN];
__device__ int   g_posvox[MAXN];
__device__ float g_ybuf[(size_t)MAXN * 32];    // stage-1 pre-BN activations, voxel-sorted
__device__ float g_zbuf[(size_t)MAXN * 128];   // stage-2 pre-BN activations, voxel-sorted
__device__ float g_xmax[(size_t)NKEY * 32];
__device__ float g_parts_s[(size_t)NBLK_MAX * 128];  // per-block BN2 partial sums
__device__ float g_parts_q[(size_t)NBLK_MAX * 128];
__device__ double g_s1[32], g_q1[32];
__device__ double g_s2[128], g_q2[128];
__device__ float g_a1[32], g_b1v[32];
__device__ float g_a2[128], g_b2v[128];
__device__ int   g_Nm;

// ---------------- K0: reset ----------------
__global__ void kzero() {
    int i = blockIdx.x * blockDim.x + threadIdx.x;
    if (i < NKEY) {
        g_cnt[i] = 0; g_cursor[i] = 0;
        g_sumx[i] = 0.f; g_sumy[i] = 0.f; g_sumz[i] = 0.f;
    }
    if (i < 32)  { g_s1[i] = 0.0; g_q1[i] = 0.0; }
    if (i == 0)  g_Nm = 0;
}

// ---------------- K1: voxelize points, per-key count + xyz sums ----------------
__global__ void k1(const float* __restrict__ pts, int n) {
    int i = blockIdx.x * blockDim.x + threadIdx.x;
    int valid = 0;
    if (i < n) {
        float bf = pts[i * 5 + 0];
        float x  = pts[i * 5 + 1];
        float y  = pts[i * 5 + 2];
        float z  = pts[i * 5 + 3];
        int cx = (int)floorf(__fdiv_rn(x - 0.0f, 0.32f));
        int cy = (int)floorf(__fdiv_rn(y + 40.0f, 0.32f));
        int cz = (int)floorf(__fdiv_rn(z + 3.0f, 4.0f));
        int key = -1;
        if (cx >= 0 && cx < 220 && cy >= 0 && cy < 250 && cz >= 0 && cz < 1) {
            key = (int)bf * 55000 + cx * 250 + cy + cz;
            atomicAdd(&g_cnt[key], 1);
            atomicAdd(&g_sumx[key], x);
            atomicAdd(&g_sumy[key], y);
            atomicAdd(&g_sumz[key], z);
            valid = 1;
        }
        g_keys[i] = key;
    }
    int c = __syncthreads_count(valid);
    if (threadIdx.x == 0) atomicAdd(&g_Nm, c);
}

// ---------------- K2: dual exclusive scan over dense key space ----------------
__global__ void k2a() {
    __shared__ unsigned long long sh[256];
    int base = blockIdx.x * 1024;
    int t = threadIdx.x;
    unsigned long long s = 0;
    #pragma unroll
    for (int j = 0; j < 4; j++) {
        int k = base + t * 4 + j;
        if (k < NKEY) {
            unsigned c = (unsigned)g_cnt[k];
            s += (((unsigned long long)(c > 0)) << 32) | (unsigned long long)c;
        }
    }
    sh[t] = s; __syncthreads();
    for (int off = 128; off > 0; off >>= 1) {
        if (t < off) sh[t] += sh[t + off];
        __syncthreads();
    }
    if (t == 0) g_bsum[blockIdx.x] = sh[0];
}

__global__ void k2b() {
    __shared__ unsigned long long sh[256];
    int t = threadIdx.x;
    unsigned long long v = (t < SCAN_BLK) ? g_bsum[t] : 0ull;
    sh[t] = v; __syncthreads();
    for (int off = 1; off < 256; off <<= 1) {
        unsigned long long a = (t >= off) ? sh[t - off] : 0ull;
        __syncthreads();
        sh[t] += a;
        __syncthreads();
    }
    if (t < SCAN_BLK) g_boff[t] = sh[t] - v;   // exclusive
}

__global__ void k2c(float* __restrict__ coords_out, int V) {
    __shared__ unsigned long long sh[256];
    int base = blockIdx.x * 1024;
    int t = threadIdx.x;
    int k0 = base + t * 4;
    unsigned long long loc[4];
    unsigned long long s = 0;
    #pragma unroll
    for (int j = 0; j < 4; j++) {
        int k = k0 + j;
        unsigned long long v = 0;
        if (k < NKEY) {
            unsigned c = (unsigned)g_cnt[k];
            v = (((unsigned long long)(c > 0)) << 32) | (unsigned long long)c;
        }
        loc[j] = s; s += v;
    }
    sh[t] = s; __syncthreads();
    for (int off = 1; off < 256; off <<= 1) {
        unsigned long long a = (t >= off) ? sh[t - off] : 0ull;
        __syncthreads();
        sh[t] += a;
        __syncthreads();
    }
    unsigned long long texcl = sh[t] - s + g_boff[blockIdx.x];
    #pragma unroll
    for (int j = 0; j < 4; j++) {
        int k = k0 + j;
        if (k >= NKEY) break;
        unsigned long long e = texcl + loc[j];
        int start = (int)(e & 0xffffffffull);
        int rank  = (int)(e >> 32);
        g_start[k] = start;
        if (g_cnt[k] > 0) {
            g_rank[k] = rank;
            g_voxstart[rank] = start;
            int b = k / 55000, rem = k % 55000;
            int cx = rem / 250, cy = rem % 250;
            if (rank < V) {
                float4 co = make_float4((float)b, 0.f, (float)cy, (float)cx);
                *(float4*)(coords_out + (size_t)rank * 4) = co;
            }
        }
    }
}

// ---------------- K3: feats -> y = feats@w0, BN1 stats, scatter into voxel order ----------------
__global__ void __launch_bounds__(256) k3(const float* __restrict__ pts,
                                          const float* __restrict__ w0, int n) {
    __shared__ float ws[10][32];
    __shared__ float sy[8][32][33];
    __shared__ int   spos[8][32];
    __shared__ int   svox[8][32];
    __shared__ float ssum[32], ssq[32];
    int t = threadIdx.x;
    for (int idx = t; idx < 320; idx += 256)
        ws[idx / 32][idx % 32] = w0[idx];
    if (t < 32) { ssum[t] = 0.f; ssq[t] = 0.f; }
    __syncthreads();

    int i = blockIdx.x * blockDim.x + t;
    int warp = t >> 5, lane = t & 31;
    int key = (i < n) ? g_keys[i] : -1;
    float y[32];
    int pos = -1, r = 0;
    if (key >= 0) {
        float x  = pts[i * 5 + 1];
        float yy = pts[i * 5 + 2];
        float z  = pts[i * 5 + 3];
        float it = pts[i * 5 + 4];
        float c  = (float)g_cnt[key];
        float mx = g_sumx[key] / c, my = g_sumy[key] / c, mz = g_sumz[key] / c;
        int rem = key % 55000;
        int cx = rem / 250, cy = rem % 250;
        float ff[10];
        ff[0] = x; ff[1] = yy; ff[2] = z; ff[3] = it;
        ff[4] = x - mx; ff[5] = yy - my; ff[6] = z - mz;
        ff[7] = x - ((float)cx * 0.32f + 0.16f);
        ff[8] = yy - ((float)cy * 0.32f - 39.84f);
        ff[9] = z + 1.0f;
        #pragma unroll
        for (int c2 = 0; c2 < 32; c2++) {
            float a = 0.f;
            #pragma unroll
            for (int j = 0; j < 10; j++) a = fmaf(ff[j], ws[j][c2], a);
            y[c2] = a;
        }
        r = g_rank[key];
        pos = g_start[key] + atomicAdd(&g_cursor[key], 1);
    } else {
        #pragma unroll
        for (int c2 = 0; c2 < 32; c2++) y[c2] = 0.f;
    }

    // BN1 stats: warp butterfly reduce per channel
    #pragma unroll
    for (int c2 = 0; c2 < 32; c2++) {
        float v = y[c2], q = v * v;
        #pragma unroll
        for (int o = 16; o > 0; o >>= 1) {
            v += __shfl_xor_sync(0xffffffffu, v, o);
            q += __shfl_xor_sync(0xffffffffu, q, o);
        }
        if (lane == c2) { atomicAdd(&ssum[c2], v); atomicAdd(&ssq[c2], q); }
    }

    // scatter y into voxel-sorted order via padded smem transpose
    #pragma unroll
    for (int c2 = 0; c2 < 32; c2++) sy[warp][lane][c2] = y[c2];
    spos[warp][lane] = pos;
    svox[warp][lane] = r;
    __syncwarp();
    for (int p = 0; p < 32; p++) {
        int dp = spos[warp][p];
        if (dp >= 0) {
            g_ybuf[(size_t)dp * 32 + lane] = sy[warp][p][lane];
            if (lane == 0) g_posvox[dp] = svox[warp][p];
        }
    }
    __syncthreads();
    if (t < 32) {
        atomicAdd(&g_s1[t], (double)ssum[t]);
        atomicAdd(&g_q1[t], (double)ssq[t]);
    }
}

// ---------------- K4: finalize BN1 params ----------------
__global__ void k4(const float* __restrict__ g0, const float* __restrict__ b0, int V) {
    int t = threadIdx.x;
    if (t == 0) g_voxstart[V] = g_Nm;
    if (t < 32) {
        double nn = (double)g_Nm;
        double m = g_s1[t] / nn;
        double var = g_q1[t] / nn - m * m;
        float s = (float)((double)g0[t] / sqrt(var + 0.001));
        g_a1[t] = s;
        g_b1v[t] = b0[t] - (float)m * s;
    }
}

// ---------------- K5: per-voxel xmax of BN1+ReLU(y) -- no writeback ----------------
__global__ void k5(int V) {
    int w = (blockIdx.x * blockDim.x + threadIdx.x) >> 5;
    int lane = threadIdx.x & 31;
    if (w >= V) return;
    int s0 = g_voxstart[w], s1 = g_voxstart[w + 1];
    float a = g_a1[lane], b = g_b1v[lane];
    float m = 0.f;
    for (int p = s0; p < s1; p++) {
        float yv = g_ybuf[(size_t)p * 32 + lane];
        m = fmaxf(m, fmaxf(fmaf(a, yv, b), 0.f));
    }
    g_xmax[(size_t)w * 32 + lane] = m;
}

// ---------------- K6: z = [h | xmax] @ w1  (fp32x2 packed, fused BN2 partial stats) ----------------
__global__ void __launch_bounds__(256) k6(const float* __restrict__ w1) {
    extern __shared__ float sm[];
    float* xs  = sm;             // [64][128] k-major, point contiguous
    float* wsh = sm + 64 * 128;  // [64][128]
    __shared__ float sa1[32], sb1[32];
    int t = threadIdx.x;
    int Nm = g_Nm;
    int P0 = blockIdx.x * 128;
    if (P0 >= Nm) {
        // inactive tile: publish zero partials so k6c can sum the full grid
        if (t < 128) {
            g_parts_s[(size_t)blockIdx.x * 128 + t] = 0.f;
            g_parts_q[(size_t)blockIdx.x * 128 + t] = 0.f;
        }
        return;
    }

    if (t < 32) { sa1[t] = g_a1[t]; sb1[t] = g_b1v[t]; }
    __syncthreads();

    for (int idx = t * 4; idx < 64 * 128; idx += 256 * 4)
        *(float4*)&wsh[idx] = *(const float4*)&w1[idx];

    {
        int p = t & 127, half = t >> 7;
        int gp = P0 + p;
        if (half == 0) {
            if (gp < Nm) {
                const float4* src = (const float4*)&g_ybuf[(size_t)gp * 32];
                #pragma unroll
                for (int q = 0; q < 8; q++) {
                    float4 v = src[q];
                    int c0 = q * 4;
                    // fused BN1 + ReLU (K5 no longer writes h back)
                    v.x = fmaxf(fmaf(sa1[c0 + 0], v.x, sb1[c0 + 0]), 0.f);
                    v.y = fmaxf(fmaf(sa1[c0 + 1], v.y, sb1[c0 + 1]), 0.f);
                    v.z = fmaxf(fmaf(sa1[c0 + 2], v.z, sb1[c0 + 2]), 0.f);
                    v.w = fmaxf(fmaf(sa1[c0 + 3], v.w, sb1[c0 + 3]), 0.f);
                    xs[(c0 + 0) * 128 + p] = v.x;
                    xs[(c0 + 1) * 128 + p] = v.y;
                    xs[(c0 + 2) * 128 + p] = v.z;
                    xs[(c0 + 3) * 128 + p] = v.w;
                }
            } else {
                #pragma unroll
                for (int k = 0; k < 32; k++) xs[k * 128 + p] = 0.f;
            }
        } else {
            if (gp < Nm) {
                int vx = g_posvox[gp];
                const float4* src = (const float4*)&g_xmax[(size_t)vx * 32];
                #pragma unroll
                for (int q = 0; q < 8; q++) {
                    float4 v = src[q];
                    xs[(32 + q * 4 + 0) * 128 + p] = v.x;
                    xs[(32 + q * 4 + 1) * 128 + p] = v.y;
                    xs[(32 + q * 4 + 2) * 128 + p] = v.z;
                    xs[(32 + q * 4 + 3) * 128 + p] = v.w;
                }
            } else {
                #pragma unroll
                for (int k = 32; k < 64; k++) xs[k * 128 + p] = 0.f;
            }
        }
    }
    __syncthreads();

    int ty = t >> 4, tx = t & 15;   // thread: points i = ty*8..+8, channels j = tx*8..+8
    // accumulators as fp32x2 pairs over adjacent channels: acc2[i][jp] = {z_j0, z_j1}
    unsigned long long acc2[8][4];
    #pragma unroll
    for (int i2 = 0; i2 < 8; i2++)
        #pragma unroll
        for (int jp = 0; jp < 4; jp++) acc2[i2][jp] = 0ull;

    #pragma unroll 4
    for (int k = 0; k < 64; k++) {
        // channel pairs come for free from the 16B shared loads (register pairs)
        ulonglong2 wA = *(const ulonglong2*)&wsh[k * 128 + tx * 8];
        ulonglong2 wB = *(const ulonglong2*)&wsh[k * 128 + tx * 8 + 4];
        float4 xa = *(const float4*)&xs[k * 128 + ty * 8];
        float4 xb = *(const float4*)&xs[k * 128 + ty * 8 + 4];
        float xr[8] = {xa.x, xa.y, xa.z, xa.w, xb.x, xb.y, xb.z, xb.w};
        unsigned long long wp0 = wA.x, wp1 = wA.y, wp2 = wB.x, wp3 = wB.y;
        #pragma unroll
        for (int i2 = 0; i2 < 8; i2++) {
            unsigned long long xi;
            PACKXX(xi, xr[i2]);
            FFMA2(acc2[i2][0], xi, wp0, acc2[i2][0]);
            FFMA2(acc2[i2][1], xi, wp1, acc2[i2][1]);
            FFMA2(acc2[i2][2], xi, wp2, acc2[i2][2]);
            FFMA2(acc2[i2][3], xi, wp3, acc2[i2][3]);
        }
    }

    // store z tiles (acc pairs are already channel-contiguous)
    int nv = Nm - P0;
    #pragma unroll
    for (int i2 = 0; i2 < 8; i2++) {
        int p = ty * 8 + i2;
        if (p < nv) {
            unsigned long long* dst =
                (unsigned long long*)&g_zbuf[((size_t)(P0 + p)) * 128 + tx * 8];
            *(ulonglong2*)(dst)     = make_ulonglong2(acc2[i2][0], acc2[i2][1]);
            *(ulonglong2*)(dst + 2) = make_ulonglong2(acc2[i2][2], acc2[i2][3]);
        }
    }

    // fused BN2 partial stats: rows beyond Nm are exact zeros -> contribute nothing
    float s8[8], q8[8];
    #pragma unroll
    for (int jj = 0; jj < 8; jj++) { s8[jj] = 0.f; q8[jj] = 0.f; }
    #pragma unroll
    for (int i2 = 0; i2 < 8; i2++) {
        #pragma unroll
        for (int jp = 0; jp < 4; jp++) {
            float2 f = *(float2*)&acc2[i2][jp];
            s8[jp * 2 + 0] += f.x;  q8[jp * 2 + 0] += f.x * f.x;
            s8[jp * 2 + 1] += f.y;  q8[jp * 2 + 1] += f.y * f.y;
        }
    }
    __syncthreads();                    // done reading xs/wsh; reuse smem
    float* rs = sm;                     // [16][128]
    float* rq = sm + 16 * 128;          // [16][128]
    #pragma unroll
    for (int jj = 0; jj < 8; jj++) {
        rs[ty * 128 + tx * 8 + jj] = s8[jj];
        rq[ty * 128 + tx * 8 + jj] = q8[jj];
    }
    __syncthreads();
    if (t < 128) {
        float S = 0.f, Q = 0.f;
        #pragma unroll
        for (int r = 0; r < 16; r++) { S += rs[r * 128 + t]; Q += rq[r * 128 + t]; }
        g_parts_s[(size_t)blockIdx.x * 128 + t] = S;
        g_parts_q[(size_t)blockIdx.x * 128 + t] = Q;
    }
}

// ---------------- K6c: reduce per-block BN2 partials in double ----------------
__global__ void k6c(int nblk) {
    __shared__ double sh[256];
    int c = blockIdx.x;        // channel 0..127
    int t = threadIdx.x;
    double s = 0.0, q = 0.0;
    for (int b = t; b < nblk; b += 256) {
        s += (double)g_parts_s[(size_t)b * 128 + c];
        q += (double)g_parts_q[(size_t)b * 128 + c];
    }
    sh[t] = s; __syncthreads();
    for (int o = 128; o > 0; o >>= 1) { if (t < o) sh[t] += sh[t + o]; __syncthreads(); }
    if (t == 0) g_s2[c] = sh[0];
    __syncthreads();
    sh[t] = q; __syncthreads();
    for (int o = 128; o > 0; o >>= 1) { if (t < o) sh[t] += sh[t + o]; __syncthreads(); }
    if (t == 0) g_q2[c] = sh[0];
}

// ---------------- K7: finalize BN2 params ----------------
__global__ void k7(const float* __restrict__ g1, const float* __restrict__ b1) {
    int t = threadIdx.x;
    double nn = (double)g_Nm;
    double m = g_s2[t] / nn;
    double var = g_q2[t] / nn - m * m;
    float s = (float)((double)g1[t] / sqrt(var + 0.001));
    g_a2[t] = s;
    g_b2v[t] = b1[t] - (float)m * s;
}

// ---------------- K8: BN2+ReLU + per-voxel max -> pillar_feat ----------------
__global__ void k8(float* __restrict__ out, int V) {
    int w = (blockIdx.x * blockDim.x + threadIdx.x) >> 5;
    int lane = threadIdx.x & 31;
    if (w >= V) return;
    int s0 = g_voxstart[w], s1 = g_voxstart[w + 1];
    float4 a = *(float4*)&g_a2[lane * 4];
    float4 b = *(float4*)&g_b2v[lane * 4];
    float4 m = make_float4(0.f, 0.f, 0.f, 0.f);
    for (int p = s0; p < s1; p++) {
        float4 z = *(float4*)&g_zbuf[(size_t)p * 128 + lane * 4];
        m.x = fmaxf(m.x, fmaxf(fmaf(a.x, z.x, b.x), 0.f));
        m.y = fmaxf(m.y, fmaxf(fmaf(a.y, z.y, b.y), 0.f));
        m.z = fmaxf(m.z, fmaxf(fmaf(a.z, z.z, b.z), 0.f));
        m.w = fmaxf(m.w, fmaxf(fmaf(a.w, z.w, b.w), 0.f));
    }
    *(float4*)&out[(size_t)w * 128 + lane * 4] = m;
}

// ---------------- host entry ----------------
extern "C" void kernel_launch(void* const* d_in, const int* in_sizes, int n_in,
                              void* d_out, int out_size) {
    const float* pts = (const float*)d_in[0];
    const float* w0  = (const float*)d_in[1];
    const float* g0  = (const float*)d_in[2];
    const float* b0  = (const float*)d_in[3];
    const float* w1  = (const float*)d_in[4];
    const float* g1  = (const float*)d_in[5];
    const float* b1  = (const float*)d_in[6];
    float* out = (float*)d_out;

    int n = in_sizes[0] / 5;
    if (n > MAXN) n = MAXN;
    int V = out_size / 132;   // output = [pillar_feat V*128 | pillar_coords V*4]
    int NB = (n + 127) / 128;

    cudaFuncSetAttribute(k6, cudaFuncAttributeMaxDynamicSharedMemorySize, 65536);

    kzero<<<(NKEY + 255) / 256, 256>>>();
    k1<<<(n + 255) / 256, 256>>>(pts, n);
    k2a<<<SCAN_BLK, 256>>>();
    k2b<<<1, 256>>>();
    k2c<<<SCAN_BLK, 256>>>(out + (size_t)V * 128, V);
    k3<<<(n + 255) / 256, 256>>>(pts, w0, n);
    k4<<<1, 32>>>(g0, b0, V);
    k5<<<(V + 7) / 8, 256>>>(V);
    k6<<<NB, 256, 65536>>>(w1);
    k6c<<<128, 256>>>(NB);
    k7<<<1, 128>>>(g1, b1);
    k8<<<(V + 7) / 8, 256>>>(out, V);
}